// round 3
// baseline (speedup 1.0000x reference)
#include <cuda_runtime.h>
#include <math_constants.h>

// Problem constants
#define NB   4
#define SL   2048
#define EMB  512
#define NH   8
#define DH   64
#define WIN  128

// ---------------------------------------------------------------------------
// Scratch (device globals: no allocations allowed)
// ---------------------------------------------------------------------------
static __device__ float g_Q[NB * NH * SL * DH];    // [b,h,s,d]
static __device__ float g_K[NB * NH * SL * DH];
static __device__ float g_V[NB * NH * SL * DH];
static __device__ float g_ctx[NB * SL * EMB];      // [b,s,e] e = h*64+d

// ---------------------------------------------------------------------------
// float atomic max via int/uint trick (target pre-initialized to -inf)
// ---------------------------------------------------------------------------
__device__ __forceinline__ void atomicMaxF(float* addr, float v) {
    if (v >= 0.0f)
        atomicMax((int*)addr, __float_as_int(v));
    else
        atomicMin((unsigned int*)addr, __float_as_uint(v));
}

__global__ void pooled_init_kernel(float* p) {
    int i = blockIdx.x * 256 + threadIdx.x;
    if (i < NB * EMB) p[i] = -CUDART_INF_F;
}

// ---------------------------------------------------------------------------
// Kernel 1: QKV projection.  C[m,n] = X[m,:]·W[n,:] + b[n], m=8192, n=1536.
// Epilogue scatters into g_Q/g_K/g_V in [b,h,s,d] layout.
// Classic 128x128x16 SGEMM, 256 threads, 8x8 microtile.
// ---------------------------------------------------------------------------
__global__ __launch_bounds__(256, 2)
void qkv_gemm_kernel(const float* __restrict__ X, const float* __restrict__ W,
                     const float* __restrict__ bias)
{
    __shared__ __align__(16) float As[16][132];
    __shared__ __align__(16) float Bs[16][132];
    const int tid  = threadIdx.x;
    const int m0   = blockIdx.y * 128;
    const int n0   = blockIdx.x * 128;
    const int mrow = (tid >> 4) << 3;
    const int ncol = (tid & 15) << 3;

    float acc[8][8];
    #pragma unroll
    for (int i = 0; i < 8; i++)
        #pragma unroll
        for (int j = 0; j < 8; j++) acc[i][j] = 0.0f;

    for (int k0 = 0; k0 < EMB; k0 += 16) {
        #pragma unroll
        for (int l = 0; l < 2; l++) {
            int f   = tid + l * 256;          // 0..511 float4 slots
            int row = f >> 2;
            int kc  = (f & 3) << 2;
            float4 av = *(const float4*)(X + (size_t)(m0 + row) * EMB + k0 + kc);
            As[kc + 0][row] = av.x; As[kc + 1][row] = av.y;
            As[kc + 2][row] = av.z; As[kc + 3][row] = av.w;
            float4 bv = *(const float4*)(W + (size_t)(n0 + row) * EMB + k0 + kc);
            Bs[kc + 0][row] = bv.x; Bs[kc + 1][row] = bv.y;
            Bs[kc + 2][row] = bv.z; Bs[kc + 3][row] = bv.w;
        }
        __syncthreads();
        #pragma unroll
        for (int kk = 0; kk < 16; kk++) {
            float4 a0 = *(const float4*)(&As[kk][mrow]);
            float4 a1 = *(const float4*)(&As[kk][mrow + 4]);
            float4 b0 = *(const float4*)(&Bs[kk][ncol]);
            float4 b1 = *(const float4*)(&Bs[kk][ncol + 4]);
            float ar[8] = {a0.x, a0.y, a0.z, a0.w, a1.x, a1.y, a1.z, a1.w};
            float br[8] = {b0.x, b0.y, b0.z, b0.w, b1.x, b1.y, b1.z, b1.w};
            #pragma unroll
            for (int i = 0; i < 8; i++)
                #pragma unroll
                for (int j = 0; j < 8; j++)
                    acc[i][j] = fmaf(ar[i], br[j], acc[i][j]);
        }
        __syncthreads();
    }

    #pragma unroll
    for (int i = 0; i < 8; i++) {
        int m  = m0 + mrow + i;
        int bb = m >> 11;           // batch
        int s  = m & (SL - 1);
        #pragma unroll
        for (int j = 0; j < 8; j += 4) {
            int n   = n0 + ncol + j;
            int sel = n >> 9;       // 0=Q 1=K 2=V  (128-tiles never straddle)
            int e   = n & (EMB - 1);
            int h   = e >> 6;
            int d   = e & 63;
            float* dst = (sel == 0) ? g_Q : (sel == 1) ? g_K : g_V;
            float4 v;
            v.x = acc[i][j + 0] + bias[n + 0];
            v.y = acc[i][j + 1] + bias[n + 1];
            v.z = acc[i][j + 2] + bias[n + 2];
            v.w = acc[i][j + 3] + bias[n + 3];
            *(float4*)(dst + (((size_t)(bb * NH + h) * SL + s) << 6) + d) = v;
        }
    }
}

// ---------------------------------------------------------------------------
// Kernel 2: banded attention. One block = (batch b, 32-query tile).
// Loops all 8 heads internally so the head-averaged weights can be
// accumulated in smem without atomics.
//   window for queries [i0, i0+31]: keys [i0-128, i0+159] -> 288 offsets,
//   padded to 3 chunks of 128 keys for the score mini-GEMM.
// smem layout (floats):
//   sQ  [64][36]   Q tile, d-major          (2304)
//   sK  [64][132]  K chunk, d-major         (8448)
//   sPT [288][36]  scores/probs, key-major  (10368)
//   sW  [288][36]  head-summed probs        (10368)
//   sV  [32][64]   V chunk                  (2048)
// total 33536 floats = 134144 bytes
// ---------------------------------------------------------------------------
#define ATT_SMEM_FLOATS 33536

__global__ __launch_bounds__(256, 1)
void attn_kernel(float* __restrict__ wout)
{
    extern __shared__ __align__(16) float sm[];
    float* sQ  = sm;
    float* sK  = sm + 2304;
    float* sPT = sm + 2304 + 8448;
    float* sW  = sPT + 10368;
    float* sV  = sW + 10368;

    const int tid  = threadIdx.x;
    const int lane = tid & 31;
    const int warp = tid >> 5;
    const int b    = blockIdx.y;
    const int i0   = blockIdx.x * 32;
    const int j0   = i0 - WIN;                 // window start (may be <0)

    // zero head-sum accumulator
    for (int idx = tid; idx < 288 * 36; idx += 256) sW[idx] = 0.0f;

    const int q0 = warp << 2;                  // score & PV q group (4 queries)
    const int kq = lane << 2;                  // score k group within chunk
    const int pd = lane << 1;                  // PV d group (2 dims)

    for (int h = 0; h < NH; h++) {
        const float* Qg = g_Q + ((size_t)(b * NH + h) * SL) * DH;
        const float* Kg = g_K + ((size_t)(b * NH + h) * SL) * DH;
        const float* Vg = g_V + ((size_t)(b * NH + h) * SL) * DH;
        __syncthreads();

        // ---- load Q tile transposed: sQ[d][q] ----
        {
            int q  = tid >> 3;
            int db = (tid & 7) << 3;
            const float* src = Qg + (size_t)(i0 + q) * DH + db;
            float4 v0 = *(const float4*)(src);
            float4 v1 = *(const float4*)(src + 4);
            float tmp[8] = {v0.x, v0.y, v0.z, v0.w, v1.x, v1.y, v1.z, v1.w};
            #pragma unroll
            for (int j = 0; j < 8; j++) sQ[(db + j) * 36 + q] = tmp[j];
        }
        __syncthreads();

        // ---- scores: 3 chunks of 128 keys ----
        for (int c = 0; c < 3; c++) {
            int kbase = j0 + c * 128;
            // load K chunk transposed sK[d][key]
            {
                int key = tid >> 1;
                int db  = (tid & 1) << 5;
                int kg  = kbase + key;
                bool ok = ((unsigned)kg < (unsigned)SL);
                const float* src = Kg + (size_t)(ok ? kg : 0) * DH + db;
                #pragma unroll
                for (int jj = 0; jj < 8; jj++) {
                    float4 v = ok ? *(const float4*)(src + jj * 4)
                                  : make_float4(0.f, 0.f, 0.f, 0.f);
                    sK[(db + jj * 4 + 0) * 132 + key] = v.x;
                    sK[(db + jj * 4 + 1) * 132 + key] = v.y;
                    sK[(db + jj * 4 + 2) * 132 + key] = v.z;
                    sK[(db + jj * 4 + 3) * 132 + key] = v.w;
                }
            }
            __syncthreads();

            float a4[4][4];
            #pragma unroll
            for (int i = 0; i < 4; i++)
                #pragma unroll
                for (int j = 0; j < 4; j++) a4[i][j] = 0.0f;

            #pragma unroll 16
            for (int d = 0; d < DH; d++) {
                float4 qf = *(const float4*)(&sQ[d * 36 + q0]);   // warp-broadcast
                float4 kf = *(const float4*)(&sK[d * 132 + kq]);
                float qa[4] = {qf.x, qf.y, qf.z, qf.w};
                float ka[4] = {kf.x, kf.y, kf.z, kf.w};
                #pragma unroll
                for (int i = 0; i < 4; i++)
                    #pragma unroll
                    for (int j = 0; j < 4; j++)
                        a4[i][j] = fmaf(qa[i], ka[j], a4[i][j]);
            }

            // mask + store (key-major)
            #pragma unroll
            for (int j = 0; j < 4; j++) {
                int o = c * 128 + kq + j;                 // window offset
                if (o < 288) {
                    int kgj = j0 + o;
                    #pragma unroll
                    for (int i = 0; i < 4; i++) {
                        int qg    = i0 + q0 + i;
                        int delta = qg - kgj;
                        bool valid = ((unsigned)kgj < (unsigned)SL) &&
                                     (delta <= WIN) && (delta >= -WIN);
                        sPT[o * 36 + q0 + i] = valid ? a4[i][j] * 0.125f : -1e30f;
                    }
                }
            }
            __syncthreads();
        }

        // ---- softmax: warp w handles queries w*4..w*4+3 ----
        for (int qq = 0; qq < 4; qq++) {
            int q = q0 + qq;
            float lv[9];
            float mx = -1e30f;
            #pragma unroll
            for (int r = 0; r < 9; r++) {
                lv[r] = sPT[(lane + r * 32) * 36 + q];
                mx = fmaxf(mx, lv[r]);
            }
            #pragma unroll
            for (int off = 16; off; off >>= 1)
                mx = fmaxf(mx, __shfl_xor_sync(0xffffffffu, mx, off));
            float sum = 0.0f;
            #pragma unroll
            for (int r = 0; r < 9; r++) { lv[r] = __expf(lv[r] - mx); sum += lv[r]; }
            #pragma unroll
            for (int off = 16; off; off >>= 1)
                sum += __shfl_xor_sync(0xffffffffu, sum, off);
            float inv = 1.0f / sum;
            #pragma unroll
            for (int r = 0; r < 9; r++) {
                float p = lv[r] * inv;
                int o = lane + r * 32;
                sPT[o * 36 + q] = p;
                sW[o * 36 + q] += p;          // one owner per (o,q): no race
            }
        }
        __syncthreads();

        // ---- PV: ctx[32q][64d] = P[32][288] @ V[288][64] ----
        float cacc[4][2];
        #pragma unroll
        for (int i = 0; i < 4; i++) { cacc[i][0] = 0.f; cacc[i][1] = 0.f; }

        for (int ch = 0; ch < 9; ch++) {
            {   // load V chunk of 32 keys
                int key = tid >> 3;
                int db  = (tid & 7) << 3;
                int kg  = j0 + ch * 32 + key;
                bool ok = ((unsigned)kg < (unsigned)SL);
                const float* src = Vg + (size_t)(ok ? kg : 0) * DH + db;
                float4 v0 = ok ? *(const float4*)(src)     : make_float4(0,0,0,0);
                float4 v1 = ok ? *(const float4*)(src + 4) : make_float4(0,0,0,0);
                *(float4*)(&sV[key * 64 + db])     = v0;
                *(float4*)(&sV[key * 64 + db + 4]) = v1;
            }
            __syncthreads();
            #pragma unroll
            for (int kk = 0; kk < 32; kk++) {
                int o = ch * 32 + kk;
                float4 pf = *(const float4*)(&sPT[o * 36 + q0]);  // warp-broadcast
                float2 vf = *(const float2*)(&sV[kk * 64 + pd]);
                float pa[4] = {pf.x, pf.y, pf.z, pf.w};
                #pragma unroll
                for (int i = 0; i < 4; i++) {
                    cacc[i][0] = fmaf(pa[i], vf.x, cacc[i][0]);
                    cacc[i][1] = fmaf(pa[i], vf.y, cacc[i][1]);
                }
            }
            __syncthreads();
        }

        // write ctx [b,s,e]
        #pragma unroll
        for (int i = 0; i < 4; i++) {
            size_t m = (size_t)b * SL + i0 + q0 + i;
            *(float2*)(&g_ctx[m * EMB + h * DH + pd]) =
                make_float2(cacc[i][0], cacc[i][1]);
        }
    }
    __syncthreads();

    // ---- write head-averaged weights (band only; rest memset to 0) ----
    float* Wb = wout + (size_t)b * SL * SL;
    for (int idx = tid; idx < 32 * 288; idx += 256) {
        int t = idx / 288;
        int o = idx - t * 288;
        int i = i0 + t;
        int j = j0 + o;
        if ((unsigned)j < (unsigned)SL && o >= t && o <= t + 256)
            Wb[(size_t)i * SL + j] = sW[o * 36 + t] * 0.125f;   // /NH
    }
}

// ---------------------------------------------------------------------------
// Kernel 3: output projection + fused max-pool over sequence.
// out[m,n] = ctx[m,:]·Wo[n,:] + bo[n];  pooled[b,n] = max_s out
// `out` is never materialized: per-block column max -> atomicMaxF.
// ---------------------------------------------------------------------------
__global__ __launch_bounds__(256, 2)
void out_gemm_kernel(const float* __restrict__ W, const float* __restrict__ bias,
                     float* __restrict__ pooled)
{
    __shared__ __align__(16) float As[16][132];
    __shared__ __align__(16) float Bs[16][132];
    __shared__ float sRed[16][128];
    const int tid  = threadIdx.x;
    const int m0   = blockIdx.y * 128;
    const int n0   = blockIdx.x * 128;
    const int mrow = (tid >> 4) << 3;
    const int ncol = (tid & 15) << 3;

    float acc[8][8];
    #pragma unroll
    for (int i = 0; i < 8; i++)
        #pragma unroll
        for (int j = 0; j < 8; j++) acc[i][j] = 0.0f;

    for (int k0 = 0; k0 < EMB; k0 += 16) {
        #pragma unroll
        for (int l = 0; l < 2; l++) {
            int f   = tid + l * 256;
            int row = f >> 2;
            int kc  = (f & 3) << 2;
            float4 av = *(const float4*)(g_ctx + (size_t)(m0 + row) * EMB + k0 + kc);
            As[kc + 0][row] = av.x; As[kc + 1][row] = av.y;
            As[kc + 2][row] = av.z; As[kc + 3][row] = av.w;
            float4 bv = *(const float4*)(W + (size_t)(n0 + row) * EMB + k0 + kc);
            Bs[kc + 0][row] = bv.x; Bs[kc + 1][row] = bv.y;
            Bs[kc + 2][row] = bv.z; Bs[kc + 3][row] = bv.w;
        }
        __syncthreads();
        #pragma unroll
        for (int kk = 0; kk < 16; kk++) {
            float4 a0 = *(const float4*)(&As[kk][mrow]);
            float4 a1 = *(const float4*)(&As[kk][mrow + 4]);
            float4 b0 = *(const float4*)(&Bs[kk][ncol]);
            float4 b1 = *(const float4*)(&Bs[kk][ncol + 4]);
            float ar[8] = {a0.x, a0.y, a0.z, a0.w, a1.x, a1.y, a1.z, a1.w};
            float br[8] = {b0.x, b0.y, b0.z, b0.w, b1.x, b1.y, b1.z, b1.w};
            #pragma unroll
            for (int i = 0; i < 8; i++)
                #pragma unroll
                for (int j = 0; j < 8; j++)
                    acc[i][j] = fmaf(ar[i], br[j], acc[i][j]);
        }
        __syncthreads();
    }

    // bias + per-thread column max over its 8 rows
    const int tr = tid >> 4;
    #pragma unroll
    for (int j = 0; j < 8; j++) {
        int n = n0 + ncol + j;
        float bj = bias[n];
        float mx = acc[0][j] + bj;
        #pragma unroll
        for (int i = 1; i < 8; i++) mx = fmaxf(mx, acc[i][j] + bj);
        sRed[tr][ncol + j] = mx;
    }
    __syncthreads();
    if (tid < 128) {
        float m = sRed[0][tid];
        #pragma unroll
        for (int g = 1; g < 16; g++) m = fmaxf(m, sRed[g][tid]);
        int bb = m0 >> 11;
        atomicMaxF(&pooled[bb * EMB + n0 + tid], m);
    }
}

// ---------------------------------------------------------------------------
// Launch
// ---------------------------------------------------------------------------
extern "C" void kernel_launch(void* const* d_in, const int* in_sizes, int n_in,
                              void* d_out, int out_size)
{
    const float *emb = nullptr, *inw = nullptr, *inb = nullptr,
                *ow = nullptr, *ob = nullptr;
    for (int i = 0; i < n_in; i++) {
        switch (in_sizes[i]) {
            case NB * SL * EMB:   emb = (const float*)d_in[i]; break;  // 4194304
            case 3 * EMB * EMB:   inw = (const float*)d_in[i]; break;  // 786432
            case 3 * EMB:         inb = (const float*)d_in[i]; break;  // 1536
            case EMB * EMB:       ow  = (const float*)d_in[i]; break;  // 262144
            case EMB:             ob  = (const float*)d_in[i]; break;  // 512
        }
    }

    float* pooled  = (float*)d_out;                 // [4, 512]
    float* weights = pooled + NB * EMB;             // [4, 2048, 2048]

    cudaMemsetAsync(weights, 0, (size_t)NB * SL * SL * sizeof(float));
    pooled_init_kernel<<<(NB * EMB + 255) / 256, 256>>>(pooled);

    qkv_gemm_kernel<<<dim3(12, 64), 256>>>(emb, inw, inb);

    cudaFuncSetAttribute(attn_kernel, cudaFuncAttributeMaxDynamicSharedMemorySize,
                         ATT_SMEM_FLOATS * sizeof(float));
    attn_kernel<<<dim3(SL / 32, NB), 256, ATT_SMEM_FLOATS * sizeof(float)>>>(weights);

    out_gemm_kernel<<<dim3(4, 64), 256>>>(ow, ob, pooled);
}

// round 5
// speedup vs baseline: 1.3057x; 1.3057x over previous
#include <cuda_runtime.h>
#include <cuda_bf16.h>
#include <math_constants.h>
#include <mma.h>

using namespace nvcuda;

// Problem constants
#define NB   4
#define SL   2048
#define EMB  512
#define NH   8
#define DH   64
#define WIN  128

// ---------------------------------------------------------------------------
// Device scratch (no allocations allowed)
// ---------------------------------------------------------------------------
static __device__ float g_Q[NB * NH * SL * DH];    // [b,h,s,d]
static __device__ float g_K[NB * NH * SL * DH];
static __device__ float g_V[NB * NH * SL * DH];
static __device__ float g_ctx[NB * SL * EMB];      // [b,s,e]
static __device__ float g_P[NB * (SL/32) * NH * 32 * 288];  // per-head probs

// ---------------------------------------------------------------------------
// float atomic max (target pre-initialized to -inf)
// ---------------------------------------------------------------------------
__device__ __forceinline__ void atomicMaxF(float* addr, float v) {
    if (v >= 0.0f) atomicMax((int*)addr, __float_as_int(v));
    else           atomicMin((unsigned int*)addr, __float_as_uint(v));
}

__global__ void pooled_init_kernel(float* p) {
    int i = blockIdx.x * 256 + threadIdx.x;
    if (i < NB * EMB) p[i] = -CUDART_INF_F;
}

// ---------------------------------------------------------------------------
// Split-bf16 WMMA GEMM core.
//   C[128x128] = A[m0..+128, 0..512] . B[n0..+128, 0..512]^T
// A, B row-major with row stride 512 (EMB). fp32 accum via 3 bf16 wmma ops.
// 8 warps, each computes 64x32 (warp grid 2x4).
// smem: 4 bf16 operand tiles [128][LDM] (K-chunk 32), then reused as
// float sC[128][132] for the epilogue.
// ---------------------------------------------------------------------------
#define KC    32
#define LDM   40
#define OPTILE (128 * LDM)               // bf16 elems per operand tile
#define SC_LD 132
#define GEMM_SMEM_BYTES (128 * SC_LD * 4 + 1024)   // sC + sRed/pad

__device__ __forceinline__ void cvt8(const float4 v0, const float4 v1,
                                     __nv_bfloat16* hi, __nv_bfloat16* lo)
{
    // 8 floats -> hi/lo bf16 at hi[0..7], lo[0..7]
    float f[8] = {v0.x, v0.y, v0.z, v0.w, v1.x, v1.y, v1.z, v1.w};
    #pragma unroll
    for (int i = 0; i < 8; i += 2) {
        __nv_bfloat162 h = __floats2bfloat162_rn(f[i], f[i + 1]);
        float2 hf = __bfloat1622float2(h);
        __nv_bfloat162 l = __floats2bfloat162_rn(f[i] - hf.x, f[i + 1] - hf.y);
        *(__nv_bfloat162*)(hi + i) = h;
        *(__nv_bfloat162*)(lo + i) = l;
    }
}

// Runs the mainloop; leaves per-warp accumulators stored into sC (row-major,
// ld=SC_LD) and returns after a final __syncthreads().
__device__ __forceinline__ void gemm_wmma(
    const float* __restrict__ A, const float* __restrict__ Bw,
    char* smem, int m0, int n0)
{
    __nv_bfloat16* sAhi = (__nv_bfloat16*)smem;
    __nv_bfloat16* sAlo = sAhi + OPTILE;
    __nv_bfloat16* sBhi = sAlo + OPTILE;
    __nv_bfloat16* sBlo = sBhi + OPTILE;

    const int tid  = threadIdx.x;
    const int wid  = tid >> 5;
    const int wm   = wid >> 2;            // 0..1  -> rows wm*64
    const int wn   = wid & 3;             // 0..3  -> cols wn*32

    wmma::fragment<wmma::accumulator, 16, 16, 16, float> acc[4][2];
    #pragma unroll
    for (int i = 0; i < 4; i++)
        #pragma unroll
        for (int j = 0; j < 2; j++) wmma::fill_fragment(acc[i][j], 0.0f);

    const int row  = tid >> 1;            // 0..127
    const int kg   = (tid & 1) * 16;      // 0 / 16
    const float* arow = A  + (size_t)(m0 + row) * EMB;
    const float* brow = Bw + (size_t)(n0 + row) * EMB;

    for (int ch = 0; ch < EMB / KC; ch++) {
        const int k0 = ch * KC;
        __syncthreads();                  // previous chunk's MMAs done
        {
            float4 a0 = *(const float4*)(arow + k0 + kg);
            float4 a1 = *(const float4*)(arow + k0 + kg + 4);
            float4 a2 = *(const float4*)(arow + k0 + kg + 8);
            float4 a3 = *(const float4*)(arow + k0 + kg + 12);
            cvt8(a0, a1, sAhi + row * LDM + kg,     sAlo + row * LDM + kg);
            cvt8(a2, a3, sAhi + row * LDM + kg + 8, sAlo + row * LDM + kg + 8);
            float4 b0 = *(const float4*)(brow + k0 + kg);
            float4 b1 = *(const float4*)(brow + k0 + kg + 4);
            float4 b2 = *(const float4*)(brow + k0 + kg + 8);
            float4 b3 = *(const float4*)(brow + k0 + kg + 12);
            cvt8(b0, b1, sBhi + row * LDM + kg,     sBlo + row * LDM + kg);
            cvt8(b2, b3, sBhi + row * LDM + kg + 8, sBlo + row * LDM + kg + 8);
        }
        __syncthreads();

        #pragma unroll
        for (int ks = 0; ks < KC / 16; ks++) {
            const int kb = ks * 16;
            wmma::fragment<wmma::matrix_a, 16, 16, 16, __nv_bfloat16,
                           wmma::row_major> ahi[4], alo[4];
            wmma::fragment<wmma::matrix_b, 16, 16, 16, __nv_bfloat16,
                           wmma::col_major> bhi[2], blo[2];
            #pragma unroll
            for (int mt = 0; mt < 4; mt++) {
                int r = (wm * 64 + mt * 16) * LDM + kb;
                wmma::load_matrix_sync(ahi[mt], sAhi + r, LDM);
                wmma::load_matrix_sync(alo[mt], sAlo + r, LDM);
            }
            #pragma unroll
            for (int nt = 0; nt < 2; nt++) {
                int r = (wn * 32 + nt * 16) * LDM + kb;
                wmma::load_matrix_sync(bhi[nt], sBhi + r, LDM);
                wmma::load_matrix_sync(blo[nt], sBlo + r, LDM);
            }
            #pragma unroll
            for (int mt = 0; mt < 4; mt++)
                #pragma unroll
                for (int nt = 0; nt < 2; nt++) {
                    wmma::mma_sync(acc[mt][nt], ahi[mt], bhi[nt], acc[mt][nt]);
                    wmma::mma_sync(acc[mt][nt], ahi[mt], blo[nt], acc[mt][nt]);
                    wmma::mma_sync(acc[mt][nt], alo[mt], bhi[nt], acc[mt][nt]);
                }
        }
    }

    __syncthreads();                      // done with operand smem
    float* sC = (float*)smem;
    #pragma unroll
    for (int mt = 0; mt < 4; mt++)
        #pragma unroll
        for (int nt = 0; nt < 2; nt++)
            wmma::store_matrix_sync(
                sC + (size_t)(wm * 64 + mt * 16) * SC_LD + wn * 32 + nt * 16,
                acc[mt][nt], SC_LD, wmma::mem_row_major);
    __syncthreads();
}

// ---------------------------------------------------------------------------
// Kernel 1: QKV projection. Epilogue scatters (with bias) into g_Q/g_K/g_V.
// ---------------------------------------------------------------------------
__global__ __launch_bounds__(256)
void qkv_tc_kernel(const float* __restrict__ X, const float* __restrict__ W,
                   const float* __restrict__ bias)
{
    extern __shared__ __align__(16) char smem[];
    const int m0 = blockIdx.y * 128, n0 = blockIdx.x * 128;
    gemm_wmma(X, W, smem, m0, n0);

    const float* sC = (const float*)smem;
    const int tid  = threadIdx.x;
    const int row  = tid >> 1;
    const int koff = (tid & 1) * 32;
    const int m    = m0 + row;
    const int bb   = m >> 11;
    const int s    = m & (SL - 1);

    #pragma unroll
    for (int ph = 0; ph < 2; ph++) {
        const int nb  = n0 + ph * 64;
        const int sel = nb >> 9;          // 0=Q 1=K 2=V
        const int h   = (nb >> 6) & 7;
        float* dst = (sel == 0) ? g_Q : (sel == 1) ? g_K : g_V;
        float* drow = dst + (((size_t)(bb * NH + h) * SL + s) << 6);
        #pragma unroll
        for (int f = 0; f < 8; f++) {
            int c = koff + f * 4;         // d index 0..63
            float4 v;
            v.x = sC[(size_t)row * SC_LD + ph * 64 + c + 0] + bias[nb + c + 0];
            v.y = sC[(size_t)row * SC_LD + ph * 64 + c + 1] + bias[nb + c + 1];
            v.z = sC[(size_t)row * SC_LD + ph * 64 + c + 2] + bias[nb + c + 2];
            v.w = sC[(size_t)row * SC_LD + ph * 64 + c + 3] + bias[nb + c + 3];
            *(float4*)(drow + c) = v;
        }
    }
}

// ---------------------------------------------------------------------------
// Kernel 2: banded attention, one block per (qtile, batch, head).
// smem: sQ[64][36] sK[64][132] sPT[288][36] sV[32][64] = 23168 floats (92KB)
// ---------------------------------------------------------------------------
#define ATT_SMEM_FLOATS 23168

__global__ __launch_bounds__(256, 2)
void attn_kernel()
{
    extern __shared__ __align__(16) float sm[];
    float* sQ  = sm;            // 2304
    float* sK  = sm + 2304;     // 8448
    float* sPT = sm + 10752;    // 10368
    float* sV  = sm + 21120;    // 2048

    const int tid  = threadIdx.x;
    const int lane = tid & 31;
    const int warp = tid >> 5;
    const int b    = blockIdx.y;
    const int h    = blockIdx.z;
    const int i0   = blockIdx.x * 32;
    const int j0   = i0 - WIN;

    const float* Qg = g_Q + ((size_t)(b * NH + h) * SL) * DH;
    const float* Kg = g_K + ((size_t)(b * NH + h) * SL) * DH;
    const float* Vg = g_V + ((size_t)(b * NH + h) * SL) * DH;

    const int q0 = warp << 2;
    const int kq = lane << 2;
    const int pd = lane << 1;

    // ---- load Q tile transposed: sQ[d][q] ----
    {
        int q  = tid >> 3;
        int db = (tid & 7) << 3;
        const float* src = Qg + (size_t)(i0 + q) * DH + db;
        float4 v0 = *(const float4*)(src);
        float4 v1 = *(const float4*)(src + 4);
        float tmp[8] = {v0.x, v0.y, v0.z, v0.w, v1.x, v1.y, v1.z, v1.w};
        #pragma unroll
        for (int j = 0; j < 8; j++) sQ[(db + j) * 36 + q] = tmp[j];
    }
    __syncthreads();

    // ---- scores: 3 chunks of 128 keys ----
    for (int c = 0; c < 3; c++) {
        int kbase = j0 + c * 128;
        {
            int key = tid >> 1;
            int db  = (tid & 1) << 5;
            int kg  = kbase + key;
            bool ok = ((unsigned)kg < (unsigned)SL);
            const float* src = Kg + (size_t)(ok ? kg : 0) * DH + db;
            #pragma unroll
            for (int jj = 0; jj < 8; jj++) {
                float4 v = ok ? *(const float4*)(src + jj * 4)
                              : make_float4(0.f, 0.f, 0.f, 0.f);
                sK[(db + jj * 4 + 0) * 132 + key] = v.x;
                sK[(db + jj * 4 + 1) * 132 + key] = v.y;
                sK[(db + jj * 4 + 2) * 132 + key] = v.z;
                sK[(db + jj * 4 + 3) * 132 + key] = v.w;
            }
        }
        __syncthreads();

        float a4[4][4];
        #pragma unroll
        for (int i = 0; i < 4; i++)
            #pragma unroll
            for (int j = 0; j < 4; j++) a4[i][j] = 0.0f;

        #pragma unroll 16
        for (int d = 0; d < DH; d++) {
            float4 qf = *(const float4*)(&sQ[d * 36 + q0]);
            float4 kf = *(const float4*)(&sK[d * 132 + kq]);
            float qa[4] = {qf.x, qf.y, qf.z, qf.w};
            float ka[4] = {kf.x, kf.y, kf.z, kf.w};
            #pragma unroll
            for (int i = 0; i < 4; i++)
                #pragma unroll
                for (int j = 0; j < 4; j++)
                    a4[i][j] = fmaf(qa[i], ka[j], a4[i][j]);
        }

        #pragma unroll
        for (int j = 0; j < 4; j++) {
            int o = c * 128 + kq + j;
            if (o < 288) {
                int kgj = j0 + o;
                #pragma unroll
                for (int i = 0; i < 4; i++) {
                    int qg    = i0 + q0 + i;
                    int delta = qg - kgj;
                    bool valid = ((unsigned)kgj < (unsigned)SL) &&
                                 (delta <= WIN) && (delta >= -WIN);
                    sPT[o * 36 + q0 + i] = valid ? a4[i][j] * 0.125f : -1e30f;
                }
            }
        }
        __syncthreads();
    }

    // ---- softmax ----
    for (int qq = 0; qq < 4; qq++) {
        int q = q0 + qq;
        float lv[9];
        float mx = -1e30f;
        #pragma unroll
        for (int r = 0; r < 9; r++) {
            lv[r] = sPT[(lane + r * 32) * 36 + q];
            mx = fmaxf(mx, lv[r]);
        }
        #pragma unroll
        for (int off = 16; off; off >>= 1)
            mx = fmaxf(mx, __shfl_xor_sync(0xffffffffu, mx, off));
        float sum = 0.0f;
        #pragma unroll
        for (int r = 0; r < 9; r++) { lv[r] = __expf(lv[r] - mx); sum += lv[r]; }
        #pragma unroll
        for (int off = 16; off; off >>= 1)
            sum += __shfl_xor_sync(0xffffffffu, sum, off);
        float inv = 1.0f / sum;
        #pragma unroll
        for (int r = 0; r < 9; r++)
            sPT[(lane + r * 32) * 36 + q] = lv[r] * inv;
    }
    __syncthreads();

    // ---- PV ----
    float cacc[4][2];
    #pragma unroll
    for (int i = 0; i < 4; i++) { cacc[i][0] = 0.f; cacc[i][1] = 0.f; }

    for (int ch = 0; ch < 9; ch++) {
        {
            int key = tid >> 3;
            int db  = (tid & 7) << 3;
            int kg  = j0 + ch * 32 + key;
            bool ok = ((unsigned)kg < (unsigned)SL);
            const float* src = Vg + (size_t)(ok ? kg : 0) * DH + db;
            float4 v0 = ok ? *(const float4*)(src)     : make_float4(0,0,0,0);
            float4 v1 = ok ? *(const float4*)(src + 4) : make_float4(0,0,0,0);
            *(float4*)(&sV[key * 64 + db])     = v0;
            *(float4*)(&sV[key * 64 + db + 4]) = v1;
        }
        __syncthreads();
        #pragma unroll
        for (int kk = 0; kk < 32; kk++) {
            int o = ch * 32 + kk;
            float4 pf = *(const float4*)(&sPT[o * 36 + q0]);
            float2 vf = *(const float2*)(&sV[kk * 64 + pd]);
            float pa[4] = {pf.x, pf.y, pf.z, pf.w};
            #pragma unroll
            for (int i = 0; i < 4; i++) {
                cacc[i][0] = fmaf(pa[i], vf.x, cacc[i][0]);
                cacc[i][1] = fmaf(pa[i], vf.y, cacc[i][1]);
            }
        }
        __syncthreads();
    }

    #pragma unroll
    for (int i = 0; i < 4; i++) {
        size_t m = (size_t)b * SL + i0 + q0 + i;
        *(float2*)(&g_ctx[m * EMB + h * DH + pd]) =
            make_float2(cacc[i][0], cacc[i][1]);
    }

    // ---- dump probs for the weights pass ----
    float* Pb = g_P + (size_t)((b * (SL / 32) + blockIdx.x) * NH + h) * (32 * 288);
    for (int idx = tid; idx < 32 * 288; idx += 256) {
        int t = idx / 288;
        int o = idx - t * 288;
        Pb[idx] = sPT[o * 36 + t];
    }
}

// ---------------------------------------------------------------------------
// Kernel 2b: head-average the probs into the banded weights output
// ---------------------------------------------------------------------------
__global__ __launch_bounds__(256)
void weights_kernel(float* __restrict__ wout)
{
    const int tile = blockIdx.x, b = blockIdx.y;
    const float* Pb = g_P + (size_t)(b * (SL / 32) + tile) * NH * (32 * 288);
    const int i0 = tile * 32, j0 = i0 - WIN;
    float* Wb = wout + (size_t)b * SL * SL;
    for (int idx = threadIdx.x; idx < 32 * 288; idx += 256) {
        float s = 0.f;
        #pragma unroll
        for (int h = 0; h < NH; h++) s += Pb[(size_t)h * (32 * 288) + idx];
        int t = idx / 288;
        int o = idx - t * 288;
        int j = j0 + o;
        if ((unsigned)j < (unsigned)SL && o >= t && o <= t + 256)
            Wb[(size_t)(i0 + t) * SL + j] = s * 0.125f;
    }
}

// ---------------------------------------------------------------------------
// Kernel 3: output projection + fused max-pool epilogue
// ---------------------------------------------------------------------------
__global__ __launch_bounds__(256)
void out_tc_kernel(const float* __restrict__ Wo, const float* __restrict__ bias,
                   float* __restrict__ pooled)
{
    extern __shared__ __align__(16) char smem[];
    const int m0 = blockIdx.y * 128, n0 = blockIdx.x * 128;
    gemm_wmma(g_ctx, Wo, smem, m0, n0);

    const float* sC   = (const float*)smem;
    float*       sRed = (float*)(smem + 128 * SC_LD * 4);   // [2][128]
    const int tid = threadIdx.x;
    const int col = tid & 127;
    const int rh  = tid >> 7;

    float m = -CUDART_INF_F;
    #pragma unroll 8
    for (int r = rh * 64; r < rh * 64 + 64; r++)
        m = fmaxf(m, sC[(size_t)r * SC_LD + col]);
    sRed[rh * 128 + col] = m;
    __syncthreads();
    if (tid < 128) {
        float v = fmaxf(sRed[tid], sRed[128 + tid]) + bias[n0 + tid];
        int bb = m0 >> 11;
        atomicMaxF(&pooled[bb * EMB + n0 + tid], v);
    }
}

// ---------------------------------------------------------------------------
// Launch
// ---------------------------------------------------------------------------
extern "C" void kernel_launch(void* const* d_in, const int* in_sizes, int n_in,
                              void* d_out, int out_size)
{
    const float *emb = nullptr, *inw = nullptr, *inb = nullptr,
                *ow = nullptr, *ob = nullptr;
    for (int i = 0; i < n_in; i++) {
        switch (in_sizes[i]) {
            case NB * SL * EMB:   emb = (const float*)d_in[i]; break;
            case 3 * EMB * EMB:   inw = (const float*)d_in[i]; break;
            case 3 * EMB:         inb = (const float*)d_in[i]; break;
            case EMB * EMB:       ow  = (const float*)d_in[i]; break;
            case EMB:             ob  = (const float*)d_in[i]; break;
        }
    }

    float* pooled  = (float*)d_out;                 // [4, 512]
    float* weights = pooled + NB * EMB;             // [4, 2048, 2048]

    cudaMemsetAsync(weights, 0, (size_t)NB * SL * SL * sizeof(float));
    pooled_init_kernel<<<(NB * EMB + 255) / 256, 256>>>(pooled);

    cudaFuncSetAttribute(qkv_tc_kernel, cudaFuncAttributeMaxDynamicSharedMemorySize,
                         GEMM_SMEM_BYTES);
    qkv_tc_kernel<<<dim3(12, 64), 256, GEMM_SMEM_BYTES>>>(emb, inw, inb);

    cudaFuncSetAttribute(attn_kernel, cudaFuncAttributeMaxDynamicSharedMemorySize,
                         ATT_SMEM_FLOATS * sizeof(float));
    attn_kernel<<<dim3(SL / 32, NB, NH), 256, ATT_SMEM_FLOATS * sizeof(float)>>>();

    weights_kernel<<<dim3(SL / 32, NB), 256>>>(weights);

    cudaFuncSetAttribute(out_tc_kernel, cudaFuncAttributeMaxDynamicSharedMemorySize,
                         GEMM_SMEM_BYTES);
    out_tc_kernel<<<dim3(4, 64), 256, GEMM_SMEM_BYTES>>>(ow, ob, pooled);
}

// round 6
// speedup vs baseline: 1.4365x; 1.1001x over previous
#include <cuda_runtime.h>
#include <cuda_bf16.h>
#include <cuda_fp16.h>
#include <math_constants.h>
#include <mma.h>

using namespace nvcuda;

// Problem constants
#define NB   4
#define SL   2048
#define EMB  512
#define NH   8
#define DH   64
#define WIN  128

// ---------------------------------------------------------------------------
// Device scratch (no allocations allowed)
// ---------------------------------------------------------------------------
static __device__ float g_Q[NB * NH * SL * DH];    // [b,h,s,d] fp32
static __device__ float g_K[NB * NH * SL * DH];
static __device__ float g_V[NB * NH * SL * DH];

static __device__ __nv_bfloat16 g_Xh[NB * SL * EMB];      // embeddings hi/lo
static __device__ __nv_bfloat16 g_Xl[NB * SL * EMB];
static __device__ __nv_bfloat16 g_Winh[3 * EMB * EMB];    // in_proj_w hi/lo
static __device__ __nv_bfloat16 g_Winl[3 * EMB * EMB];
static __device__ __nv_bfloat16 g_Wouth[EMB * EMB];       // out_w hi/lo
static __device__ __nv_bfloat16 g_Woutl[EMB * EMB];
static __device__ __nv_bfloat16 g_ctxh[NB * SL * EMB];    // ctx hi/lo
static __device__ __nv_bfloat16 g_ctxl[NB * SL * EMB];

static __device__ __half g_P[NB * (SL/32) * NH * 32 * 288];  // per-head probs

// ---------------------------------------------------------------------------
// float atomic max (target pre-initialized to -inf)
// ---------------------------------------------------------------------------
__device__ __forceinline__ void atomicMaxF(float* addr, float v) {
    if (v >= 0.0f) atomicMax((int*)addr, __float_as_int(v));
    else           atomicMin((unsigned int*)addr, __float_as_uint(v));
}

__global__ void pooled_init_kernel(float* p) {
    int i = blockIdx.x * 256 + threadIdx.x;
    if (i < NB * EMB) p[i] = -CUDART_INF_F;
}

// ---------------------------------------------------------------------------
// Prep: split fp32 tensor into bf16 hi/lo pair (one shot, reused by GEMMs)
// which: 0 = X, 1 = W_in, 2 = W_out
// ---------------------------------------------------------------------------
__global__ __launch_bounds__(256)
void split_kernel(const float* __restrict__ src, int which, int n4)
{
    __nv_bfloat16 *hi, *lo;
    if (which == 0)      { hi = g_Xh;    lo = g_Xl; }
    else if (which == 1) { hi = g_Winh;  lo = g_Winl; }
    else                 { hi = g_Wouth; lo = g_Woutl; }

    int i = blockIdx.x * 256 + threadIdx.x;
    if (i >= n4) return;
    float4 v = ((const float4*)src)[i];
    __nv_bfloat162 h01 = __floats2bfloat162_rn(v.x, v.y);
    __nv_bfloat162 h23 = __floats2bfloat162_rn(v.z, v.w);
    float2 f01 = __bfloat1622float2(h01);
    float2 f23 = __bfloat1622float2(h23);
    __nv_bfloat162 l01 = __floats2bfloat162_rn(v.x - f01.x, v.y - f01.y);
    __nv_bfloat162 l23 = __floats2bfloat162_rn(v.z - f23.x, v.w - f23.y);
    uint2 hv, lv;
    hv.x = *(unsigned*)&h01; hv.y = *(unsigned*)&h23;
    lv.x = *(unsigned*)&l01; lv.y = *(unsigned*)&l23;
    ((uint2*)hi)[i] = hv;
    ((uint2*)lo)[i] = lv;
}

// ---------------------------------------------------------------------------
// Split-bf16 WMMA GEMM core (pre-split operands).
//   C[128x128] = A[m0..+128, 0..512] . B[n0..+128, 0..512]^T
// A, B given as bf16 hi/lo, row-major stride EMB. fp32 accum, 3 wmma per tile.
// 8 warps, each 64x32 (warp grid 2x4). K-chunk 64.
// smem: 4 bf16 tiles [128][72]; reused as float sC[128][132] in epilogue.
// ---------------------------------------------------------------------------
#define KC    64
#define LDM   72
#define OPTILE (128 * LDM)
#define SC_LD 132
#define GEMM_SMEM_BYTES (4 * OPTILE * 2)   // 73728 B

__device__ __forceinline__ void gemm_wmma(
    const __nv_bfloat16* __restrict__ Ah, const __nv_bfloat16* __restrict__ Al,
    const __nv_bfloat16* __restrict__ Bh, const __nv_bfloat16* __restrict__ Bl,
    char* smem, int m0, int n0)
{
    __nv_bfloat16* sAhi = (__nv_bfloat16*)smem;
    __nv_bfloat16* sAlo = sAhi + OPTILE;
    __nv_bfloat16* sBhi = sAlo + OPTILE;
    __nv_bfloat16* sBlo = sBhi + OPTILE;

    const int tid = threadIdx.x;
    const int wid = tid >> 5;
    const int wm  = wid >> 2;             // 0..1  -> rows wm*64
    const int wn  = wid & 3;              // 0..3  -> cols wn*32

    wmma::fragment<wmma::accumulator, 16, 16, 16, float> acc[4][2];
    #pragma unroll
    for (int i = 0; i < 4; i++)
        #pragma unroll
        for (int j = 0; j < 2; j++) wmma::fill_fragment(acc[i][j], 0.0f);

    const int row = tid >> 1;             // 0..127
    const int kg  = (tid & 1) * 32;       // 0 / 32
    const __nv_bfloat16* pAh = Ah + (size_t)(m0 + row) * EMB + kg;
    const __nv_bfloat16* pAl = Al + (size_t)(m0 + row) * EMB + kg;
    const __nv_bfloat16* pBh = Bh + (size_t)(n0 + row) * EMB + kg;
    const __nv_bfloat16* pBl = Bl + (size_t)(n0 + row) * EMB + kg;
    __nv_bfloat16* dA_h = sAhi + row * LDM + kg;
    __nv_bfloat16* dA_l = sAlo + row * LDM + kg;
    __nv_bfloat16* dB_h = sBhi + row * LDM + kg;
    __nv_bfloat16* dB_l = sBlo + row * LDM + kg;

    for (int ch = 0; ch < EMB / KC; ch++) {
        const int k0 = ch * KC;
        __syncthreads();                  // previous chunk's MMAs done
        #pragma unroll
        for (int u = 0; u < 4; u++) {     // 4 x 16B per operand array
            *(uint4*)(dA_h + u * 8) = *(const uint4*)(pAh + k0 + u * 8);
            *(uint4*)(dA_l + u * 8) = *(const uint4*)(pAl + k0 + u * 8);
            *(uint4*)(dB_h + u * 8) = *(const uint4*)(pBh + k0 + u * 8);
            *(uint4*)(dB_l + u * 8) = *(const uint4*)(pBl + k0 + u * 8);
        }
        __syncthreads();

        #pragma unroll
        for (int ks = 0; ks < KC / 16; ks++) {
            const int kb = ks * 16;
            wmma::fragment<wmma::matrix_a, 16, 16, 16, __nv_bfloat16,
                           wmma::row_major> ahi[4], alo[4];
            wmma::fragment<wmma::matrix_b, 16, 16, 16, __nv_bfloat16,
                           wmma::col_major> bhi[2], blo[2];
            #pragma unroll
            for (int mt = 0; mt < 4; mt++) {
                int r = (wm * 64 + mt * 16) * LDM + kb;
                wmma::load_matrix_sync(ahi[mt], sAhi + r, LDM);
                wmma::load_matrix_sync(alo[mt], sAlo + r, LDM);
            }
            #pragma unroll
            for (int nt = 0; nt < 2; nt++) {
                int r = (wn * 32 + nt * 16) * LDM + kb;
                wmma::load_matrix_sync(bhi[nt], sBhi + r, LDM);
                wmma::load_matrix_sync(blo[nt], sBlo + r, LDM);
            }
            #pragma unroll
            for (int mt = 0; mt < 4; mt++)
                #pragma unroll
                for (int nt = 0; nt < 2; nt++) {
                    wmma::mma_sync(acc[mt][nt], ahi[mt], bhi[nt], acc[mt][nt]);
                    wmma::mma_sync(acc[mt][nt], ahi[mt], blo[nt], acc[mt][nt]);
                    wmma::mma_sync(acc[mt][nt], alo[mt], bhi[nt], acc[mt][nt]);
                }
        }
    }

    __syncthreads();                      // done with operand smem
    float* sC = (float*)smem;
    #pragma unroll
    for (int mt = 0; mt < 4; mt++)
        #pragma unroll
        for (int nt = 0; nt < 2; nt++)
            wmma::store_matrix_sync(
                sC + (size_t)(wm * 64 + mt * 16) * SC_LD + wn * 32 + nt * 16,
                acc[mt][nt], SC_LD, wmma::mem_row_major);
    __syncthreads();
}

// ---------------------------------------------------------------------------
// Kernel 1: QKV projection. Epilogue scatters (with bias) into g_Q/g_K/g_V.
// ---------------------------------------------------------------------------
__global__ __launch_bounds__(256)
void qkv_tc_kernel(const float* __restrict__ bias)
{
    extern __shared__ __align__(16) char smem[];
    const int m0 = blockIdx.y * 128, n0 = blockIdx.x * 128;
    gemm_wmma(g_Xh, g_Xl, g_Winh, g_Winl, smem, m0, n0);

    const float* sC = (const float*)smem;
    const int tid  = threadIdx.x;
    const int row  = tid >> 1;
    const int koff = (tid & 1) * 32;
    const int m    = m0 + row;
    const int bb   = m >> 11;
    const int s    = m & (SL - 1);

    #pragma unroll
    for (int ph = 0; ph < 2; ph++) {
        const int nb  = n0 + ph * 64;
        const int sel = nb >> 9;          // 0=Q 1=K 2=V
        const int hh  = (nb >> 6) & 7;
        float* dst = (sel == 0) ? g_Q : (sel == 1) ? g_K : g_V;
        float* drow = dst + (((size_t)(bb * NH + hh) * SL + s) << 6);
        #pragma unroll
        for (int f = 0; f < 8; f++) {
            int c = koff + f * 4;         // d index 0..63
            float4 v;
            v.x = sC[(size_t)row * SC_LD + ph * 64 + c + 0] + bias[nb + c + 0];
            v.y = sC[(size_t)row * SC_LD + ph * 64 + c + 1] + bias[nb + c + 1];
            v.z = sC[(size_t)row * SC_LD + ph * 64 + c + 2] + bias[nb + c + 2];
            v.w = sC[(size_t)row * SC_LD + ph * 64 + c + 3] + bias[nb + c + 3];
            *(float4*)(drow + c) = v;
        }
    }
}

// ---------------------------------------------------------------------------
// Kernel 2: banded attention, one block per (qtile, batch, head).
// smem: sQ[64][36] sK[64][132] sPT[288][36] sV[32][64] = 23168 floats (92KB)
// Emits ctx as bf16 hi/lo, probs as fp16.
// ---------------------------------------------------------------------------
#define ATT_SMEM_FLOATS 23168

__global__ __launch_bounds__(256, 2)
void attn_kernel()
{
    extern __shared__ __align__(16) float sm[];
    float* sQ  = sm;            // 2304
    float* sK  = sm + 2304;     // 8448
    float* sPT = sm + 10752;    // 10368
    float* sV  = sm + 21120;    // 2048

    const int tid  = threadIdx.x;
    const int lane = tid & 31;
    const int warp = tid >> 5;
    const int b    = blockIdx.y;
    const int h    = blockIdx.z;
    const int i0   = blockIdx.x * 32;
    const int j0   = i0 - WIN;

    const float* Qg = g_Q + ((size_t)(b * NH + h) * SL) * DH;
    const float* Kg = g_K + ((size_t)(b * NH + h) * SL) * DH;
    const float* Vg = g_V + ((size_t)(b * NH + h) * SL) * DH;

    const int q0 = warp << 2;
    const int kq = lane << 2;
    const int pd = lane << 1;

    // ---- load Q tile transposed: sQ[d][q] ----
    {
        int q  = tid >> 3;
        int db = (tid & 7) << 3;
        const float* src = Qg + (size_t)(i0 + q) * DH + db;
        float4 v0 = *(const float4*)(src);
        float4 v1 = *(const float4*)(src + 4);
        float tmp[8] = {v0.x, v0.y, v0.z, v0.w, v1.x, v1.y, v1.z, v1.w};
        #pragma unroll
        for (int j = 0; j < 8; j++) sQ[(db + j) * 36 + q] = tmp[j];
    }
    __syncthreads();

    // ---- scores: 3 chunks of 128 keys ----
    for (int c = 0; c < 3; c++) {
        int kbase = j0 + c * 128;
        {
            int key = tid >> 1;
            int db  = (tid & 1) << 5;
            int kg  = kbase + key;
            bool ok = ((unsigned)kg < (unsigned)SL);
            const float* src = Kg + (size_t)(ok ? kg : 0) * DH + db;
            #pragma unroll
            for (int jj = 0; jj < 8; jj++) {
                float4 v = ok ? *(const float4*)(src + jj * 4)
                              : make_float4(0.f, 0.f, 0.f, 0.f);
                sK[(db + jj * 4 + 0) * 132 + key] = v.x;
                sK[(db + jj * 4 + 1) * 132 + key] = v.y;
                sK[(db + jj * 4 + 2) * 132 + key] = v.z;
                sK[(db + jj * 4 + 3) * 132 + key] = v.w;
            }
        }
        __syncthreads();

        float a4[4][4];
        #pragma unroll
        for (int i = 0; i < 4; i++)
            #pragma unroll
            for (int j = 0; j < 4; j++) a4[i][j] = 0.0f;

        #pragma unroll 16
        for (int d = 0; d < DH; d++) {
            float4 qf = *(const float4*)(&sQ[d * 36 + q0]);
            float4 kf = *(const float4*)(&sK[d * 132 + kq]);
            float qa[4] = {qf.x, qf.y, qf.z, qf.w};
            float ka[4] = {kf.x, kf.y, kf.z, kf.w};
            #pragma unroll
            for (int i = 0; i < 4; i++)
                #pragma unroll
                for (int j = 0; j < 4; j++)
                    a4[i][j] = fmaf(qa[i], ka[j], a4[i][j]);
        }

        #pragma unroll
        for (int j = 0; j < 4; j++) {
            int o = c * 128 + kq + j;
            if (o < 288) {
                int kgj = j0 + o;
                #pragma unroll
                for (int i = 0; i < 4; i++) {
                    int qg    = i0 + q0 + i;
                    int delta = qg - kgj;
                    bool valid = ((unsigned)kgj < (unsigned)SL) &&
                                 (delta <= WIN) && (delta >= -WIN);
                    sPT[o * 36 + q0 + i] = valid ? a4[i][j] * 0.125f : -1e30f;
                }
            }
        }
        __syncthreads();
    }

    // ---- softmax ----
    for (int qq = 0; qq < 4; qq++) {
        int q = q0 + qq;
        float lv[9];
        float mx = -1e30f;
        #pragma unroll
        for (int r = 0; r < 9; r++) {
            lv[r] = sPT[(lane + r * 32) * 36 + q];
            mx = fmaxf(mx, lv[r]);
        }
        #pragma unroll
        for (int off = 16; off; off >>= 1)
            mx = fmaxf(mx, __shfl_xor_sync(0xffffffffu, mx, off));
        float sum = 0.0f;
        #pragma unroll
        for (int r = 0; r < 9; r++) { lv[r] = __expf(lv[r] - mx); sum += lv[r]; }
        #pragma unroll
        for (int off = 16; off; off >>= 1)
            sum += __shfl_xor_sync(0xffffffffu, sum, off);
        float inv = 1.0f / sum;
        #pragma unroll
        for (int r = 0; r < 9; r++)
            sPT[(lane + r * 32) * 36 + q] = lv[r] * inv;
    }
    __syncthreads();

    // ---- PV ----
    float cacc[4][2];
    #pragma unroll
    for (int i = 0; i < 4; i++) { cacc[i][0] = 0.f; cacc[i][1] = 0.f; }

    for (int ch = 0; ch < 9; ch++) {
        {
            int key = tid >> 3;
            int db  = (tid & 7) << 3;
            int kg  = j0 + ch * 32 + key;
            bool ok = ((unsigned)kg < (unsigned)SL);
            const float* src = Vg + (size_t)(ok ? kg : 0) * DH + db;
            float4 v0 = ok ? *(const float4*)(src)     : make_float4(0,0,0,0);
            float4 v1 = ok ? *(const float4*)(src + 4) : make_float4(0,0,0,0);
            *(float4*)(&sV[key * 64 + db])     = v0;
            *(float4*)(&sV[key * 64 + db + 4]) = v1;
        }
        __syncthreads();
        #pragma unroll
        for (int kk = 0; kk < 32; kk++) {
            int o = ch * 32 + kk;
            float4 pf = *(const float4*)(&sPT[o * 36 + q0]);
            float2 vf = *(const float2*)(&sV[kk * 64 + pd]);
            float pa[4] = {pf.x, pf.y, pf.z, pf.w};
            #pragma unroll
            for (int i = 0; i < 4; i++) {
                cacc[i][0] = fmaf(pa[i], vf.x, cacc[i][0]);
                cacc[i][1] = fmaf(pa[i], vf.y, cacc[i][1]);
            }
        }
        __syncthreads();
    }

    // ---- ctx as bf16 hi/lo ----
    #pragma unroll
    for (int i = 0; i < 4; i++) {
        size_t m   = (size_t)b * SL + i0 + q0 + i;
        size_t off = m * EMB + h * DH + pd;
        float vx = cacc[i][0], vy = cacc[i][1];
        __nv_bfloat162 hv = __floats2bfloat162_rn(vx, vy);
        float2 hf = __bfloat1622float2(hv);
        __nv_bfloat162 lv = __floats2bfloat162_rn(vx - hf.x, vy - hf.y);
        *(__nv_bfloat162*)(g_ctxh + off) = hv;
        *(__nv_bfloat162*)(g_ctxl + off) = lv;
    }

    // ---- dump probs (fp16) for the weights pass ----
    __half* Pb = g_P + (size_t)((b * (SL / 32) + blockIdx.x) * NH + h) * (32 * 288);
    for (int idx2 = tid; idx2 < 32 * 144; idx2 += 256) {
        int idx = idx2 * 2;
        int t = idx / 288;
        int o = idx - t * 288;
        __half2 hv = __floats2half2_rn(sPT[o * 36 + t], sPT[(o + 1) * 36 + t]);
        *(__half2*)(Pb + idx) = hv;
    }
}

// ---------------------------------------------------------------------------
// Kernel 2b: head-average the probs into the banded weights output
// ---------------------------------------------------------------------------
__global__ __launch_bounds__(256)
void weights_kernel(float* __restrict__ wout)
{
    const int tile = blockIdx.x, b = blockIdx.y;
    const __half* Pb = g_P + (size_t)(b * (SL / 32) + tile) * NH * (32 * 288);
    const int i0 = tile * 32, j0 = i0 - WIN;
    float* Wb = wout + (size_t)b * SL * SL;
    for (int idx2 = threadIdx.x; idx2 < 32 * 144; idx2 += 256) {
        int idx = idx2 * 2;
        float2 s = make_float2(0.f, 0.f);
        #pragma unroll
        for (int h = 0; h < NH; h++) {
            __half2 v = *(const __half2*)(Pb + (size_t)h * (32 * 288) + idx);
            float2 f = __half22float2(v);
            s.x += f.x; s.y += f.y;
        }
        int t = idx / 288;
        int o = idx - t * 288;
        int i = i0 + t;
        #pragma unroll
        for (int e = 0; e < 2; e++) {
            int oe = o + e;
            int j  = j0 + oe;
            float val = e ? s.y : s.x;
            if ((unsigned)j < (unsigned)SL && oe >= t && oe <= t + 256)
                Wb[(size_t)i * SL + j] = val * 0.125f;
        }
    }
}

// ---------------------------------------------------------------------------
// Kernel 3: output projection + fused max-pool epilogue
// ---------------------------------------------------------------------------
__global__ __launch_bounds__(256)
void out_tc_kernel(const float* __restrict__ bias, float* __restrict__ pooled)
{
    extern __shared__ __align__(16) char smem[];
    const int m0 = blockIdx.y * 128, n0 = blockIdx.x * 128;
    gemm_wmma(g_ctxh, g_ctxl, g_Wouth, g_Woutl, smem, m0, n0);

    const float* sC   = (const float*)smem;
    float*       sRed = (float*)(smem + 128 * SC_LD * 4);   // [2][128]
    const int tid = threadIdx.x;
    const int col = tid & 127;
    const int rh  = tid >> 7;

    float m = -CUDART_INF_F;
    #pragma unroll 8
    for (int r = rh * 64; r < rh * 64 + 64; r++)
        m = fmaxf(m, sC[(size_t)r * SC_LD + col]);
    sRed[rh * 128 + col] = m;
    __syncthreads();
    if (tid < 128) {
        float v = fmaxf(sRed[tid], sRed[128 + tid]) + bias[n0 + tid];
        int bb = m0 >> 11;
        atomicMaxF(&pooled[bb * EMB + n0 + tid], v);
    }
}

// ---------------------------------------------------------------------------
// Launch
// ---------------------------------------------------------------------------
extern "C" void kernel_launch(void* const* d_in, const int* in_sizes, int n_in,
                              void* d_out, int out_size)
{
    const float *emb = nullptr, *inw = nullptr, *inb = nullptr,
                *ow = nullptr, *ob = nullptr;
    for (int i = 0; i < n_in; i++) {
        switch (in_sizes[i]) {
            case NB * SL * EMB:   emb = (const float*)d_in[i]; break;
            case 3 * EMB * EMB:   inw = (const float*)d_in[i]; break;
            case 3 * EMB:         inb = (const float*)d_in[i]; break;
            case EMB * EMB:       ow  = (const float*)d_in[i]; break;
            case EMB:             ob  = (const float*)d_in[i]; break;
        }
    }

    float* pooled  = (float*)d_out;                 // [4, 512]
    float* weights = pooled + NB * EMB;             // [4, 2048, 2048]

    cudaMemsetAsync(weights, 0, (size_t)NB * SL * SL * sizeof(float));
    pooled_init_kernel<<<(NB * EMB + 255) / 256, 256>>>(pooled);

    // one-shot bf16 hi/lo splits
    split_kernel<<<(NB * SL * EMB / 4 + 255) / 256, 256>>>(emb, 0, NB * SL * EMB / 4);
    split_kernel<<<(3 * EMB * EMB / 4 + 255) / 256, 256>>>(inw, 1, 3 * EMB * EMB / 4);
    split_kernel<<<(EMB * EMB / 4 + 255) / 256, 256>>>(ow, 2, EMB * EMB / 4);

    cudaFuncSetAttribute(qkv_tc_kernel, cudaFuncAttributeMaxDynamicSharedMemorySize,
                         GEMM_SMEM_BYTES);
    qkv_tc_kernel<<<dim3(12, 64), 256, GEMM_SMEM_BYTES>>>(inb);

    cudaFuncSetAttribute(attn_kernel, cudaFuncAttributeMaxDynamicSharedMemorySize,
                         ATT_SMEM_FLOATS * sizeof(float));
    attn_kernel<<<dim3(SL / 32, NB, NH), 256, ATT_SMEM_FLOATS * sizeof(float)>>>();

    weights_kernel<<<dim3(SL / 32, NB), 256>>>(weights);

    cudaFuncSetAttribute(out_tc_kernel, cudaFuncAttributeMaxDynamicSharedMemorySize,
                         GEMM_SMEM_BYTES);
    out_tc_kernel<<<dim3(4, 64), 256, GEMM_SMEM_BYTES>>>(ob, pooled);
}

// round 7
// speedup vs baseline: 1.6522x; 1.1502x over previous
#include <cuda_runtime.h>
#include <cuda_bf16.h>
#include <math_constants.h>
#include <mma.h>

using namespace nvcuda;

// Problem constants
#define NB   4
#define SL   2048
#define EMB  512
#define NH   8
#define DH   64
#define WIN  128

// ---------------------------------------------------------------------------
// Device scratch (no allocations allowed)
// ---------------------------------------------------------------------------
static __device__ __nv_bfloat16 g_Qh[NB * NH * SL * DH];  // [b,h,s,d] hi/lo
static __device__ __nv_bfloat16 g_Ql[NB * NH * SL * DH];
static __device__ __nv_bfloat16 g_Kh[NB * NH * SL * DH];
static __device__ __nv_bfloat16 g_Kl[NB * NH * SL * DH];
static __device__ __nv_bfloat16 g_Vh[NB * NH * SL * DH];
static __device__ __nv_bfloat16 g_Vl[NB * NH * SL * DH];

static __device__ __nv_bfloat16 g_Xh[NB * SL * EMB];      // embeddings hi/lo
static __device__ __nv_bfloat16 g_Xl[NB * SL * EMB];
static __device__ __nv_bfloat16 g_Winh[3 * EMB * EMB];    // in_proj_w hi/lo
static __device__ __nv_bfloat16 g_Winl[3 * EMB * EMB];
static __device__ __nv_bfloat16 g_Wouth[EMB * EMB];       // out_w hi/lo
static __device__ __nv_bfloat16 g_Woutl[EMB * EMB];
static __device__ __nv_bfloat16 g_ctxh[NB * SL * EMB];    // ctx hi/lo
static __device__ __nv_bfloat16 g_ctxl[NB * SL * EMB];

// ---------------------------------------------------------------------------
// float atomic max (target pre-initialized to -inf)
// ---------------------------------------------------------------------------
__device__ __forceinline__ void atomicMaxF(float* addr, float v) {
    if (v >= 0.0f) atomicMax((int*)addr, __float_as_int(v));
    else           atomicMin((unsigned int*)addr, __float_as_uint(v));
}

__global__ void pooled_init_kernel(float* p) {
    int i = blockIdx.x * 256 + threadIdx.x;
    if (i < NB * EMB) p[i] = -CUDART_INF_F;
}

// ---------------------------------------------------------------------------
// Prep: split fp32 tensor into bf16 hi/lo pair
// which: 0 = X, 1 = W_in, 2 = W_out
// ---------------------------------------------------------------------------
__global__ __launch_bounds__(256)
void split_kernel(const float* __restrict__ src, int which, int n4)
{
    __nv_bfloat16 *hi, *lo;
    if (which == 0)      { hi = g_Xh;    lo = g_Xl; }
    else if (which == 1) { hi = g_Winh;  lo = g_Winl; }
    else                 { hi = g_Wouth; lo = g_Woutl; }

    int i = blockIdx.x * 256 + threadIdx.x;
    if (i >= n4) return;
    float4 v = ((const float4*)src)[i];
    __nv_bfloat162 h01 = __floats2bfloat162_rn(v.x, v.y);
    __nv_bfloat162 h23 = __floats2bfloat162_rn(v.z, v.w);
    float2 f01 = __bfloat1622float2(h01);
    float2 f23 = __bfloat1622float2(h23);
    __nv_bfloat162 l01 = __floats2bfloat162_rn(v.x - f01.x, v.y - f01.y);
    __nv_bfloat162 l23 = __floats2bfloat162_rn(v.z - f23.x, v.w - f23.y);
    uint2 hv, lv;
    hv.x = *(unsigned*)&h01; hv.y = *(unsigned*)&h23;
    lv.x = *(unsigned*)&l01; lv.y = *(unsigned*)&l23;
    ((uint2*)hi)[i] = hv;
    ((uint2*)lo)[i] = lv;
}

// ---------------------------------------------------------------------------
// Split-bf16 WMMA GEMM core (pre-split operands).
//   C[128x128] = A[m0..+128, 0..512] . B[n0..+128, 0..512]^T
// ---------------------------------------------------------------------------
#define KC    64
#define LDM   72
#define OPTILE (128 * LDM)
#define SC_LD 132
#define GEMM_SMEM_BYTES (4 * OPTILE * 2)   // 73728 B

__device__ __forceinline__ void gemm_wmma(
    const __nv_bfloat16* __restrict__ Ah, const __nv_bfloat16* __restrict__ Al,
    const __nv_bfloat16* __restrict__ Bh, const __nv_bfloat16* __restrict__ Bl,
    char* smem, int m0, int n0)
{
    __nv_bfloat16* sAhi = (__nv_bfloat16*)smem;
    __nv_bfloat16* sAlo = sAhi + OPTILE;
    __nv_bfloat16* sBhi = sAlo + OPTILE;
    __nv_bfloat16* sBlo = sBhi + OPTILE;

    const int tid = threadIdx.x;
    const int wid = tid >> 5;
    const int wm  = wid >> 2;
    const int wn  = wid & 3;

    wmma::fragment<wmma::accumulator, 16, 16, 16, float> acc[4][2];
    #pragma unroll
    for (int i = 0; i < 4; i++)
        #pragma unroll
        for (int j = 0; j < 2; j++) wmma::fill_fragment(acc[i][j], 0.0f);

    const int row = tid >> 1;
    const int kg  = (tid & 1) * 32;
    const __nv_bfloat16* pAh = Ah + (size_t)(m0 + row) * EMB + kg;
    const __nv_bfloat16* pAl = Al + (size_t)(m0 + row) * EMB + kg;
    const __nv_bfloat16* pBh = Bh + (size_t)(n0 + row) * EMB + kg;
    const __nv_bfloat16* pBl = Bl + (size_t)(n0 + row) * EMB + kg;
    __nv_bfloat16* dA_h = sAhi + row * LDM + kg;
    __nv_bfloat16* dA_l = sAlo + row * LDM + kg;
    __nv_bfloat16* dB_h = sBhi + row * LDM + kg;
    __nv_bfloat16* dB_l = sBlo + row * LDM + kg;

    for (int ch = 0; ch < EMB / KC; ch++) {
        const int k0 = ch * KC;
        __syncthreads();
        #pragma unroll
        for (int u = 0; u < 4; u++) {
            *(uint4*)(dA_h + u * 8) = *(const uint4*)(pAh + k0 + u * 8);
            *(uint4*)(dA_l + u * 8) = *(const uint4*)(pAl + k0 + u * 8);
            *(uint4*)(dB_h + u * 8) = *(const uint4*)(pBh + k0 + u * 8);
            *(uint4*)(dB_l + u * 8) = *(const uint4*)(pBl + k0 + u * 8);
        }
        __syncthreads();

        #pragma unroll
        for (int ks = 0; ks < KC / 16; ks++) {
            const int kb = ks * 16;
            wmma::fragment<wmma::matrix_a, 16, 16, 16, __nv_bfloat16,
                           wmma::row_major> ahi[4], alo[4];
            wmma::fragment<wmma::matrix_b, 16, 16, 16, __nv_bfloat16,
                           wmma::col_major> bhi[2], blo[2];
            #pragma unroll
            for (int mt = 0; mt < 4; mt++) {
                int r = (wm * 64 + mt * 16) * LDM + kb;
                wmma::load_matrix_sync(ahi[mt], sAhi + r, LDM);
                wmma::load_matrix_sync(alo[mt], sAlo + r, LDM);
            }
            #pragma unroll
            for (int nt = 0; nt < 2; nt++) {
                int r = (wn * 32 + nt * 16) * LDM + kb;
                wmma::load_matrix_sync(bhi[nt], sBhi + r, LDM);
                wmma::load_matrix_sync(blo[nt], sBlo + r, LDM);
            }
            #pragma unroll
            for (int mt = 0; mt < 4; mt++)
                #pragma unroll
                for (int nt = 0; nt < 2; nt++) {
                    wmma::mma_sync(acc[mt][nt], ahi[mt], bhi[nt], acc[mt][nt]);
                    wmma::mma_sync(acc[mt][nt], ahi[mt], blo[nt], acc[mt][nt]);
                    wmma::mma_sync(acc[mt][nt], alo[mt], bhi[nt], acc[mt][nt]);
                }
        }
    }

    __syncthreads();
    float* sC = (float*)smem;
    #pragma unroll
    for (int mt = 0; mt < 4; mt++)
        #pragma unroll
        for (int nt = 0; nt < 2; nt++)
            wmma::store_matrix_sync(
                sC + (size_t)(wm * 64 + mt * 16) * SC_LD + wn * 32 + nt * 16,
                acc[mt][nt], SC_LD, wmma::mem_row_major);
    __syncthreads();
}

// ---------------------------------------------------------------------------
// Kernel 1: QKV projection. Epilogue adds bias and scatters bf16 hi/lo
// into g_Qh/l, g_Kh/l, g_Vh/l [b,h,s,d].
// ---------------------------------------------------------------------------
__global__ __launch_bounds__(256)
void qkv_tc_kernel(const float* __restrict__ bias)
{
    extern __shared__ __align__(16) char smem[];
    const int m0 = blockIdx.y * 128, n0 = blockIdx.x * 128;
    gemm_wmma(g_Xh, g_Xl, g_Winh, g_Winl, smem, m0, n0);

    const float* sC = (const float*)smem;
    const int tid  = threadIdx.x;
    const int row  = tid >> 1;
    const int koff = (tid & 1) * 32;
    const int m    = m0 + row;
    const int bb   = m >> 11;
    const int s    = m & (SL - 1);

    #pragma unroll
    for (int ph = 0; ph < 2; ph++) {
        const int nb  = n0 + ph * 64;
        const int sel = nb >> 9;          // 0=Q 1=K 2=V
        const int hh  = (nb >> 6) & 7;
        __nv_bfloat16* dh = (sel == 0) ? g_Qh : (sel == 1) ? g_Kh : g_Vh;
        __nv_bfloat16* dl = (sel == 0) ? g_Ql : (sel == 1) ? g_Kl : g_Vl;
        size_t base = (((size_t)(bb * NH + hh) * SL + s) << 6);
        #pragma unroll
        for (int f = 0; f < 8; f++) {
            int c = koff + f * 4;
            float4 v;
            v.x = sC[(size_t)row * SC_LD + ph * 64 + c + 0] + bias[nb + c + 0];
            v.y = sC[(size_t)row * SC_LD + ph * 64 + c + 1] + bias[nb + c + 1];
            v.z = sC[(size_t)row * SC_LD + ph * 64 + c + 2] + bias[nb + c + 2];
            v.w = sC[(size_t)row * SC_LD + ph * 64 + c + 3] + bias[nb + c + 3];
            __nv_bfloat162 h01 = __floats2bfloat162_rn(v.x, v.y);
            __nv_bfloat162 h23 = __floats2bfloat162_rn(v.z, v.w);
            float2 f01 = __bfloat1622float2(h01);
            float2 f23 = __bfloat1622float2(h23);
            __nv_bfloat162 l01 = __floats2bfloat162_rn(v.x - f01.x, v.y - f01.y);
            __nv_bfloat162 l23 = __floats2bfloat162_rn(v.z - f23.x, v.w - f23.y);
            uint2 hv, lv;
            hv.x = *(unsigned*)&h01; hv.y = *(unsigned*)&h23;
            lv.x = *(unsigned*)&l01; lv.y = *(unsigned*)&l23;
            *(uint2*)(dh + base + c) = hv;
            *(uint2*)(dl + base + c) = lv;
        }
    }
}

// ---------------------------------------------------------------------------
// Kernel 2: banded attention — wmma, loop over heads, register weight accum.
// One block = (32-query tile, batch). 8 warps.
// smem: sQ hi/lo [32][72]b (9216 B, reused as sCtx fp32 [32][68])
//       sK hi/lo [128][72]b (36864 B, reused for V chunks)
//       sS fp32 [32][392] (50176 B, reused in-place as P hi/lo [32][392]b x2)
// total 96256 B -> 2 CTAs/SM, grid 256 = one wave.
// ---------------------------------------------------------------------------
#define AT_SMEM_BYTES (9216 + 36864 + 50176)

__global__ __launch_bounds__(256, 2)
void attn_kernel(float* __restrict__ wout)
{
    extern __shared__ __align__(16) char smem[];
    __nv_bfloat16* sQh = (__nv_bfloat16*)smem;            // 32*72
    __nv_bfloat16* sQl = sQh + 32 * 72;
    __nv_bfloat16* sKh = (__nv_bfloat16*)(smem + 9216);   // 128*72
    __nv_bfloat16* sKl = sKh + 128 * 72;
    float*         sS  = (float*)(smem + 9216 + 36864);   // 32*392
    __nv_bfloat16* sP  = (__nv_bfloat16*)sS;  // row q: hi at q*784+o, lo +392
    float*         sCtx = (float*)smem;                   // 32*68 (reuse sQ)

    const int tid  = threadIdx.x;
    const int lane = tid & 31;
    const int warp = tid >> 5;
    const int b    = blockIdx.y;
    const int i0   = blockIdx.x * 32;
    const int j0   = i0 - WIN;

    float wsum[36];
    #pragma unroll
    for (int i = 0; i < 36; i++) wsum[i] = 0.0f;

    // per-thread load coords
    const int qrow = tid >> 3, qdp = (tid & 7) * 8;       // Q loads
    const int krow = tid >> 1, kdp = (tid & 1) * 32;      // K/V loads

    for (int h = 0; h < NH; h++) {
        __syncthreads();    // prev head's sCtx reads & P reads done

        // ---- load Q tile hi/lo ----
        {
            size_t off = ((size_t)(b * NH + h) * SL + i0 + qrow) * DH + qdp;
            *(uint4*)(sQh + qrow * 72 + qdp) = *(const uint4*)(g_Qh + off);
            *(uint4*)(sQl + qrow * 72 + qdp) = *(const uint4*)(g_Ql + off);
        }

        // ---- QK scores: 3 chunks of 128 keys ----
        for (int c = 0; c < 3; c++) {
            int kg = j0 + c * 128 + krow;
            bool ok = ((unsigned)kg < (unsigned)SL);
            size_t off = ((size_t)(b * NH + h) * SL + (ok ? kg : 0)) * DH + kdp;
            const uint4 z = make_uint4(0, 0, 0, 0);
            #pragma unroll
            for (int u = 0; u < 4; u++) {
                *(uint4*)(sKh + krow * 72 + kdp + u * 8) =
                    ok ? *(const uint4*)(g_Kh + off + u * 8) : z;
                *(uint4*)(sKl + krow * 72 + kdp + u * 8) =
                    ok ? *(const uint4*)(g_Kl + off + u * 8) : z;
            }
            __syncthreads();

            wmma::fragment<wmma::accumulator, 16, 16, 16, float> acc[2];
            wmma::fill_fragment(acc[0], 0.0f);
            wmma::fill_fragment(acc[1], 0.0f);
            #pragma unroll
            for (int kt = 0; kt < 4; kt++) {
                wmma::fragment<wmma::matrix_b, 16, 16, 16, __nv_bfloat16,
                               wmma::col_major> bhi, blo;
                wmma::load_matrix_sync(bhi, sKh + warp * 16 * 72 + kt * 16, 72);
                wmma::load_matrix_sync(blo, sKl + warp * 16 * 72 + kt * 16, 72);
                #pragma unroll
                for (int mt = 0; mt < 2; mt++) {
                    wmma::fragment<wmma::matrix_a, 16, 16, 16, __nv_bfloat16,
                                   wmma::row_major> ahi, alo;
                    wmma::load_matrix_sync(ahi, sQh + mt * 16 * 72 + kt * 16, 72);
                    wmma::load_matrix_sync(alo, sQl + mt * 16 * 72 + kt * 16, 72);
                    wmma::mma_sync(acc[mt], ahi, bhi, acc[mt]);
                    wmma::mma_sync(acc[mt], ahi, blo, acc[mt]);
                    wmma::mma_sync(acc[mt], alo, bhi, acc[mt]);
                }
            }
            #pragma unroll
            for (int mt = 0; mt < 2; mt++)
                wmma::store_matrix_sync(sS + mt * 16 * 392 + c * 128 + warp * 16,
                                        acc[mt], 392, wmma::mem_row_major);
            __syncthreads();
        }

        // ---- softmax + in-place P split (warp owns rows warp*4..+3) ----
        #pragma unroll
        for (int qq = 0; qq < 4; qq++) {
            const int q = warp * 4 + qq;
            const float* Sr = sS + q * 392;
            float lv[9];
            float mx = -1e30f;
            #pragma unroll
            for (int r = 0; r < 9; r++) {
                int o = lane + r * 32;
                int j = j0 + o;
                int dlt = (i0 + q) - j;
                bool valid = ((unsigned)j < (unsigned)SL) &&
                             (dlt <= WIN) && (dlt >= -WIN);
                lv[r] = valid ? Sr[o] * 0.125f : -1e30f;
                mx = fmaxf(mx, lv[r]);
            }
            #pragma unroll
            for (int off = 16; off; off >>= 1)
                mx = fmaxf(mx, __shfl_xor_sync(0xffffffffu, mx, off));
            float sum = 0.0f;
            #pragma unroll
            for (int r = 0; r < 9; r++) { lv[r] = __expf(lv[r] - mx); sum += lv[r]; }
            #pragma unroll
            for (int off = 16; off; off >>= 1)
                sum += __shfl_xor_sync(0xffffffffu, sum, off);
            float inv = 1.0f / sum;
            // all reads of this row done (shfl = warp barrier) -> safe in-place
            __nv_bfloat16* Ph = sP + q * 784;
            __nv_bfloat16* Pl = Ph + 392;
            #pragma unroll
            for (int r = 0; r < 9; r++) {
                float p = lv[r] * inv;
                int o = lane + r * 32;
                __nv_bfloat16 hi = __float2bfloat16_rn(p);
                __nv_bfloat16 lo = __float2bfloat16_rn(p - __bfloat162float(hi));
                Ph[o] = hi;
                Pl[o] = lo;
                wsum[r * 4 + qq] += p;
            }
            #pragma unroll
            for (int r = 9; r < 12; r++) {       // zero pad cols 288..383
                int o = lane + r * 32;
                Ph[o] = __float2bfloat16_rn(0.0f);
                Pl[o] = __float2bfloat16_rn(0.0f);
            }
        }
        __syncthreads();

        // ---- PV: ctx[32][64] = P[32][384] @ V[384][64] ----
        const int wm = warp >> 2, wn = warp & 3;
        wmma::fragment<wmma::accumulator, 16, 16, 16, float> accv;
        wmma::fill_fragment(accv, 0.0f);

        for (int c2 = 0; c2 < 3; c2++) {
            int kg = j0 + c2 * 128 + krow;
            bool ok = ((unsigned)kg < (unsigned)SL);
            size_t off = ((size_t)(b * NH + h) * SL + (ok ? kg : 0)) * DH + kdp;
            const uint4 z = make_uint4(0, 0, 0, 0);
            #pragma unroll
            for (int u = 0; u < 4; u++) {
                *(uint4*)(sKh + krow * 72 + kdp + u * 8) =
                    ok ? *(const uint4*)(g_Vh + off + u * 8) : z;
                *(uint4*)(sKl + krow * 72 + kdp + u * 8) =
                    ok ? *(const uint4*)(g_Vl + off + u * 8) : z;
            }
            __syncthreads();

            #pragma unroll
            for (int kt = 0; kt < 8; kt++) {
                int k = c2 * 128 + kt * 16;
                wmma::fragment<wmma::matrix_a, 16, 16, 16, __nv_bfloat16,
                               wmma::row_major> phi, plo;
                wmma::load_matrix_sync(phi, sP + wm * 16 * 784 + k, 784);
                wmma::load_matrix_sync(plo, sP + wm * 16 * 784 + 392 + k, 784);
                wmma::fragment<wmma::matrix_b, 16, 16, 16, __nv_bfloat16,
                               wmma::row_major> vhi, vlo;
                wmma::load_matrix_sync(vhi, sKh + kt * 16 * 72 + wn * 16, 72);
                wmma::load_matrix_sync(vlo, sKl + kt * 16 * 72 + wn * 16, 72);
                wmma::mma_sync(accv, phi, vhi, accv);
                wmma::mma_sync(accv, phi, vlo, accv);
                wmma::mma_sync(accv, plo, vhi, accv);
            }
            __syncthreads();
        }

        // store ctx tile to sCtx (overwrites sQ region — Q no longer needed)
        wmma::store_matrix_sync(sCtx + wm * 16 * 68 + wn * 16, accv, 68,
                                wmma::mem_row_major);
        __syncthreads();

        // write ctx as bf16 hi/lo: thread handles 8 consecutive d of one row
        {
            int r = tid >> 3, dp = (tid & 7) * 8;
            const float* src = sCtx + r * 68 + dp;
            size_t doff = ((size_t)b * SL + i0 + r) * EMB + h * DH + dp;
            unsigned hv[4], lv2[4];
            #pragma unroll
            for (int u = 0; u < 4; u++) {
                float x = src[u * 2], y = src[u * 2 + 1];
                __nv_bfloat162 hh2 = __floats2bfloat162_rn(x, y);
                float2 hf = __bfloat1622float2(hh2);
                __nv_bfloat162 ll2 = __floats2bfloat162_rn(x - hf.x, y - hf.y);
                hv[u] = *(unsigned*)&hh2;
                lv2[u] = *(unsigned*)&ll2;
            }
            *(uint4*)(g_ctxh + doff) = *(uint4*)hv;
            *(uint4*)(g_ctxl + doff) = *(uint4*)lv2;
        }
    }

    // ---- weights epilogue: head-averaged probs from registers ----
    float* Wb = wout + (size_t)b * SL * SL;
    #pragma unroll
    for (int qq = 0; qq < 4; qq++) {
        int i = i0 + warp * 4 + qq;
        #pragma unroll
        for (int r = 0; r < 9; r++) {
            int o = lane + r * 32;
            int j = j0 + o;
            int dlt = i - j;
            if ((unsigned)j < (unsigned)SL && dlt <= WIN && dlt >= -WIN)
                Wb[(size_t)i * SL + j] = wsum[r * 4 + qq] * 0.125f;
        }
    }
}

// ---------------------------------------------------------------------------
// Kernel 3: output projection + fused max-pool epilogue
// ---------------------------------------------------------------------------
__global__ __launch_bounds__(256)
void out_tc_kernel(const float* __restrict__ bias, float* __restrict__ pooled)
{
    extern __shared__ __align__(16) char smem[];
    const int m0 = blockIdx.y * 128, n0 = blockIdx.x * 128;
    gemm_wmma(g_ctxh, g_ctxl, g_Wouth, g_Woutl, smem, m0, n0);

    const float* sC   = (const float*)smem;
    float*       sRed = (float*)(smem + 128 * SC_LD * 4);   // [2][128]
    const int tid = threadIdx.x;
    const int col = tid & 127;
    const int rh  = tid >> 7;

    float m = -CUDART_INF_F;
    #pragma unroll 8
    for (int r = rh * 64; r < rh * 64 + 64; r++)
        m = fmaxf(m, sC[(size_t)r * SC_LD + col]);
    sRed[rh * 128 + col] = m;
    __syncthreads();
    if (tid < 128) {
        float v = fmaxf(sRed[tid], sRed[128 + tid]) + bias[n0 + tid];
        int bb = m0 >> 11;
        atomicMaxF(&pooled[bb * EMB + n0 + tid], v);
    }
}

// ---------------------------------------------------------------------------
// Launch
// ---------------------------------------------------------------------------
extern "C" void kernel_launch(void* const* d_in, const int* in_sizes, int n_in,
                              void* d_out, int out_size)
{
    const float *emb = nullptr, *inw = nullptr, *inb = nullptr,
                *ow = nullptr, *ob = nullptr;
    for (int i = 0; i < n_in; i++) {
        switch (in_sizes[i]) {
            case NB * SL * EMB:   emb = (const float*)d_in[i]; break;
            case 3 * EMB * EMB:   inw = (const float*)d_in[i]; break;
            case 3 * EMB:         inb = (const float*)d_in[i]; break;
            case EMB * EMB:       ow  = (const float*)d_in[i]; break;
            case EMB:             ob  = (const float*)d_in[i]; break;
        }
    }

    float* pooled  = (float*)d_out;                 // [4, 512]
    float* weights = pooled + NB * EMB;             // [4, 2048, 2048]

    cudaMemsetAsync(weights, 0, (size_t)NB * SL * SL * sizeof(float));
    pooled_init_kernel<<<(NB * EMB + 255) / 256, 256>>>(pooled);

    // one-shot bf16 hi/lo splits
    split_kernel<<<(NB * SL * EMB / 4 + 255) / 256, 256>>>(emb, 0, NB * SL * EMB / 4);
    split_kernel<<<(3 * EMB * EMB / 4 + 255) / 256, 256>>>(inw, 1, 3 * EMB * EMB / 4);
    split_kernel<<<(EMB * EMB / 4 + 255) / 256, 256>>>(ow, 2, EMB * EMB / 4);

    cudaFuncSetAttribute(qkv_tc_kernel, cudaFuncAttributeMaxDynamicSharedMemorySize,
                         GEMM_SMEM_BYTES);
    qkv_tc_kernel<<<dim3(12, 64), 256, GEMM_SMEM_BYTES>>>(inb);

    cudaFuncSetAttribute(attn_kernel, cudaFuncAttributeMaxDynamicSharedMemorySize,
                         AT_SMEM_BYTES);
    attn_kernel<<<dim3(SL / 32, NB), 256, AT_SMEM_BYTES>>>(weights);

    cudaFuncSetAttribute(out_tc_kernel, cudaFuncAttributeMaxDynamicSharedMemorySize,
                         GEMM_SMEM_BYTES);
    out_tc_kernel<<<dim3(4, 64), 256, GEMM_SMEM_BYTES>>>(ob, pooled);
}